// round 6
// baseline (speedup 1.0000x reference)
#include <cuda_runtime.h>
#include <math.h>

#define B_  64
#define C_  512
#define HW_ 4096      // 64*64
#define E_  16
#define K_  4

#define ROWS_PER_BLK 8           // 8 warps/block, 1 row/warp
#define BLKS_PER_B   (C_ / ROWS_PER_BLK)   // 64 blocks per batch

__device__ float g_pooled[B_ * C_];
__device__ int   g_count[B_];    // zero-init; reset to 0 by the gating block

// ---------------------------------------------------------------------------
// Fused: pool all rows; the LAST block to finish a batch computes its gate.
// launch_bounds(256, 8) caps regs at 32 so the cold gate tail cannot hurt
// occupancy (pool loop needs ~20 regs; tail spills are cold-path only).
// ---------------------------------------------------------------------------
__global__ __launch_bounds__(256, 8) void fused_gate_kernel(
    const float* __restrict__ x,
    const float* __restrict__ W0, const float* __restrict__ b0,
    const float* __restrict__ W1, const float* __restrict__ b1,
    float* __restrict__ out) {

    const int tid  = threadIdx.x;
    const int wid  = tid >> 5;
    const int lane = tid & 31;
    const int row  = blockIdx.x * ROWS_PER_BLK + wid;   // (b,c) row
    const int b    = blockIdx.x / BLKS_PER_B;

    __shared__ float sh_h[E_];
    __shared__ float sh_n[E_];
    __shared__ int   sh_last;

    // ---------------- pool: max + mean over 4096 contiguous floats ----------
    {
        const float4* __restrict__ p =
            reinterpret_cast<const float4*>(x + (size_t)row * HW_);
        float mx0 = -INFINITY, mx1 = -INFINITY;
        float sm0 = 0.0f, sm1 = 0.0f;
#pragma unroll
        for (int i = 0; i < HW_ / 4 / 32; i += 2) {   // 32 float4/lane, 2 chains
            float4 a = p[i * 32 + lane];
            float4 c = p[(i + 1) * 32 + lane];
            mx0 = fmaxf(mx0, fmaxf(fmaxf(a.x, a.y), fmaxf(a.z, a.w)));
            sm0 += (a.x + a.y) + (a.z + a.w);
            mx1 = fmaxf(mx1, fmaxf(fmaxf(c.x, c.y), fmaxf(c.z, c.w)));
            sm1 += (c.x + c.y) + (c.z + c.w);
        }
        float mx = fmaxf(mx0, mx1);
        float sm = sm0 + sm1;
#pragma unroll
        for (int o = 16; o; o >>= 1) {
            mx = fmaxf(mx, __shfl_xor_sync(0xffffffffu, mx, o));
            sm += __shfl_xor_sync(0xffffffffu, sm, o);
        }
        if (lane == 0) g_pooled[row] = mx + sm * (1.0f / HW_);
    }

    // ---------------- block-level completion protocol -----------------------
    __syncthreads();                      // all 8 rows of this block stored
    if (tid == 0) {
        __threadfence();                  // release our g_pooled writes
        sh_last = (atomicAdd(&g_count[b], 1) == BLKS_PER_B - 1);
    }
    __syncthreads();
    if (!sh_last) return;
    __threadfence();                      // acquire all batch-b writes

    // ---------------- gate for batch b: 8 warps, 2 experts per warp ---------
    {
        const float4* __restrict__ prow =
            reinterpret_cast<const float4*>(g_pooled + b * C_);
        float4 pv[4];
#pragma unroll
        for (int i = 0; i < 4; i++) pv[i] = prow[lane + 32 * i];

#pragma unroll
        for (int t = 0; t < 2; t++) {
            const int e = wid * 2 + t;
            const float4* __restrict__ w0p =
                reinterpret_cast<const float4*>(W0 + e * C_);
            const float4* __restrict__ w1p =
                reinterpret_cast<const float4*>(W1 + e * C_);
            float d0 = 0.0f, d1 = 0.0f;
#pragma unroll
            for (int i = 0; i < 4; i++) {
                float4 w0 = w0p[lane + 32 * i];
                float4 w1 = w1p[lane + 32 * i];
                d0 = fmaf(pv[i].x, w0.x, d0); d0 = fmaf(pv[i].y, w0.y, d0);
                d0 = fmaf(pv[i].z, w0.z, d0); d0 = fmaf(pv[i].w, w0.w, d0);
                d1 = fmaf(pv[i].x, w1.x, d1); d1 = fmaf(pv[i].y, w1.y, d1);
                d1 = fmaf(pv[i].z, w1.z, d1); d1 = fmaf(pv[i].w, w1.w, d1);
            }
#pragma unroll
            for (int o = 16; o; o >>= 1) {
                d0 += __shfl_xor_sync(0xffffffffu, d0, o);
                d1 += __shfl_xor_sync(0xffffffffu, d1, o);
            }
            if (lane == 0) {
                float hv = d0 + b0[e];
                sh_h[e] = (hv >= 0.0f) ? hv : 0.2f * hv;             // LeakyReLU
                float z = d1 + b1[e];
                sh_n[e] = fmaxf(z, 0.0f) + log1pf(expf(-fabsf(z)));  // softplus
            }
        }
    }
    __syncthreads();

    // ---------------- scalar epilogue on thread 0 ---------------------------
    if (tid == 0) {
        float h[E_], nz[E_];
#pragma unroll
        for (int i = 0; i < E_; i++) { h[i] = sh_h[i]; nz[i] = sh_n[i]; }

        float mu = 0.0f;
#pragma unroll
        for (int i = 0; i < E_; i++) mu += nz[i];
        mu *= (1.0f / E_);

        float var = 0.0f;
#pragma unroll
        for (int i = 0; i < E_; i++) { float d = nz[i] - mu; var += d * d; }
        float sd = sqrtf(var * (1.0f / (E_ - 1)));       // ddof=1

        float score[E_];
#pragma unroll
        for (int i = 0; i < E_; i++) score[i] = h[i] + (nz[i] - mu) / sd;

        // top-K; strict '>' = first-occurrence tie-break like jax.lax.top_k
        bool sel[E_];
#pragma unroll
        for (int i = 0; i < E_; i++) sel[i] = false;
        for (int k = 0; k < K_; k++) {
            int   best = -1;
            float bv   = -INFINITY;
#pragma unroll
            for (int i = 0; i < E_; i++) {
                if (!sel[i] && score[i] > bv) { bv = score[i]; best = i; }
            }
            sel[best] = true;
        }

        float mh = -INFINITY;
#pragma unroll
        for (int i = 0; i < E_; i++) if (sel[i]) mh = fmaxf(mh, h[i]);
        float s = 0.0f;
        float g[E_];
#pragma unroll
        for (int i = 0; i < E_; i++) {
            g[i] = sel[i] ? expf(h[i] - mh) : 0.0f;
            s += g[i];
        }
        float inv = 1.0f / s;
#pragma unroll
        for (int i = 0; i < E_; i++) out[b * E_ + i] = g[i] * inv;

        g_count[b] = 0;   // reset for next graph replay (deterministic)
    }
}

// ---------------------------------------------------------------------------
extern "C" void kernel_launch(void* const* d_in, const int* in_sizes, int n_in,
                              void* d_out, int out_size) {
    const float* x  = (const float*)d_in[0];
    const float* W0 = (const float*)d_in[1];
    const float* b0 = (const float*)d_in[2];
    const float* W1 = (const float*)d_in[3];
    const float* b1 = (const float*)d_in[4];
    float* out = (float*)d_out;

    fused_gate_kernel<<<(B_ * C_) / ROWS_PER_BLK, 256>>>(x, W0, b0, W1, b1, out);
}

// round 7
// speedup vs baseline: 1.0170x; 1.0170x over previous
#include <cuda_runtime.h>
#include <math.h>

#define B_  64
#define C_  512
#define HW_ 4096      // 64*64
#define E_  16
#define K_  4

#define ROWS_PER_BLK 8                      // 8 warps/block, 1 row/warp
#define BLKS_PER_B   (C_ / ROWS_PER_BLK)    // 64 blocks per batch

__device__ float g_pooled[B_ * C_];
__device__ int   g_count[B_];    // zero-init; reset to 0 by the gating block

// ---------------------------------------------------------------------------
// Cold gate tail: __noinline__ so its register pressure is ABI-contained and
// cannot shrink the hot pool loop's load window. Runs in 64 blocks total.
// All 256 threads of the last-arriving block enter (uniform), so the
// __syncthreads inside is legal.
// ---------------------------------------------------------------------------
__device__ __noinline__ void gate_tail(int b,
                                       const float* __restrict__ W0,
                                       const float* __restrict__ b0,
                                       const float* __restrict__ W1,
                                       const float* __restrict__ b1,
                                       float* __restrict__ out) {
    __shared__ float sh_h[E_];
    __shared__ float sh_n[E_];

    const int tid  = threadIdx.x;
    const int wid  = tid >> 5;
    const int lane = tid & 31;

    const float4* __restrict__ prow =
        reinterpret_cast<const float4*>(g_pooled + b * C_);
    float4 pv[4];
#pragma unroll
    for (int i = 0; i < 4; i++) pv[i] = prow[lane + 32 * i];

#pragma unroll
    for (int t = 0; t < 2; t++) {
        const int e = wid * 2 + t;
        const float4* __restrict__ w0p =
            reinterpret_cast<const float4*>(W0 + e * C_);
        const float4* __restrict__ w1p =
            reinterpret_cast<const float4*>(W1 + e * C_);
        float d0 = 0.0f, d1 = 0.0f;
#pragma unroll
        for (int i = 0; i < 4; i++) {
            float4 w0 = w0p[lane + 32 * i];
            float4 w1 = w1p[lane + 32 * i];
            d0 = fmaf(pv[i].x, w0.x, d0); d0 = fmaf(pv[i].y, w0.y, d0);
            d0 = fmaf(pv[i].z, w0.z, d0); d0 = fmaf(pv[i].w, w0.w, d0);
            d1 = fmaf(pv[i].x, w1.x, d1); d1 = fmaf(pv[i].y, w1.y, d1);
            d1 = fmaf(pv[i].z, w1.z, d1); d1 = fmaf(pv[i].w, w1.w, d1);
        }
#pragma unroll
        for (int o = 16; o; o >>= 1) {
            d0 += __shfl_xor_sync(0xffffffffu, d0, o);
            d1 += __shfl_xor_sync(0xffffffffu, d1, o);
        }
        if (lane == 0) {
            float hv = d0 + b0[e];
            sh_h[e] = (hv >= 0.0f) ? hv : 0.2f * hv;             // LeakyReLU
            float z = d1 + b1[e];
            sh_n[e] = fmaxf(z, 0.0f) + log1pf(expf(-fabsf(z)));  // softplus
        }
    }
    __syncthreads();

    if (tid == 0) {
        float h[E_], nz[E_];
#pragma unroll
        for (int i = 0; i < E_; i++) { h[i] = sh_h[i]; nz[i] = sh_n[i]; }

        float mu = 0.0f;
#pragma unroll
        for (int i = 0; i < E_; i++) mu += nz[i];
        mu *= (1.0f / E_);

        float var = 0.0f;
#pragma unroll
        for (int i = 0; i < E_; i++) { float d = nz[i] - mu; var += d * d; }
        float sd = sqrtf(var * (1.0f / (E_ - 1)));       // ddof=1

        float score[E_];
#pragma unroll
        for (int i = 0; i < E_; i++) score[i] = h[i] + (nz[i] - mu) / sd;

        // top-K; strict '>' = first-occurrence tie-break like jax.lax.top_k
        bool sel[E_];
#pragma unroll
        for (int i = 0; i < E_; i++) sel[i] = false;
        for (int k = 0; k < K_; k++) {
            int   best = -1;
            float bv   = -INFINITY;
#pragma unroll
            for (int i = 0; i < E_; i++) {
                if (!sel[i] && score[i] > bv) { bv = score[i]; best = i; }
            }
            sel[best] = true;
        }

        float mh = -INFINITY;
#pragma unroll
        for (int i = 0; i < E_; i++) if (sel[i]) mh = fmaxf(mh, h[i]);
        float s = 0.0f;
        float g[E_];
#pragma unroll
        for (int i = 0; i < E_; i++) {
            g[i] = sel[i] ? expf(h[i] - mh) : 0.0f;
            s += g[i];
        }
        float inv = 1.0f / s;
#pragma unroll
        for (int i = 0; i < E_; i++) out[b * E_ + i] = g[i] * inv;

        g_count[b] = 0;   // reset for next graph replay (deterministic)
    }
}

// ---------------------------------------------------------------------------
// Fused: pool all rows; the LAST block to finish a batch computes its gate.
// launch_bounds(256, 6) leaves ~42 regs for the pool loop's load window.
// ---------------------------------------------------------------------------
__global__ __launch_bounds__(256, 6) void fused_gate_kernel(
    const float* __restrict__ x,
    const float* __restrict__ W0, const float* __restrict__ b0,
    const float* __restrict__ W1, const float* __restrict__ b1,
    float* __restrict__ out) {

    const int tid  = threadIdx.x;
    const int wid  = tid >> 5;
    const int lane = tid & 31;
    const int row  = blockIdx.x * ROWS_PER_BLK + wid;   // (b,c) row
    const int b    = blockIdx.x / BLKS_PER_B;

    __shared__ int sh_last;

    // ---------------- pool: max + mean over 4096 contiguous floats ----------
    {
        const float4* __restrict__ p =
            reinterpret_cast<const float4*>(x + (size_t)row * HW_);
        float mx0 = -INFINITY, mx1 = -INFINITY;
        float sm0 = 0.0f, sm1 = 0.0f;
#pragma unroll
        for (int i = 0; i < HW_ / 4 / 32; i += 2) {   // 32 float4/lane, 2 chains
            float4 a = p[i * 32 + lane];
            float4 c = p[(i + 1) * 32 + lane];
            mx0 = fmaxf(mx0, fmaxf(fmaxf(a.x, a.y), fmaxf(a.z, a.w)));
            sm0 += (a.x + a.y) + (a.z + a.w);
            mx1 = fmaxf(mx1, fmaxf(fmaxf(c.x, c.y), fmaxf(c.z, c.w)));
            sm1 += (c.x + c.y) + (c.z + c.w);
        }
        float mx = fmaxf(mx0, mx1);
        float sm = sm0 + sm1;
#pragma unroll
        for (int o = 16; o; o >>= 1) {
            mx = fmaxf(mx, __shfl_xor_sync(0xffffffffu, mx, o));
            sm += __shfl_xor_sync(0xffffffffu, sm, o);
        }
        if (lane == 0) g_pooled[row] = mx + sm * (1.0f / HW_);
    }

    // ---------------- block-level completion protocol -----------------------
    __syncthreads();                      // all 8 rows of this block stored
    if (tid == 0) {
        __threadfence();                  // release our g_pooled writes
        sh_last = (atomicAdd(&g_count[b], 1) == BLKS_PER_B - 1);
    }
    __syncthreads();
    if (!sh_last) return;
    __threadfence();                      // acquire all batch-b writes

    gate_tail(b, W0, b0, W1, b1, out);
}

// ---------------------------------------------------------------------------
extern "C" void kernel_launch(void* const* d_in, const int* in_sizes, int n_in,
                              void* d_out, int out_size) {
    const float* x  = (const float*)d_in[0];
    const float* W0 = (const float*)d_in[1];
    const float* b0 = (const float*)d_in[2];
    const float* W1 = (const float*)d_in[3];
    const float* b1 = (const float*)d_in[4];
    float* out = (float*)d_out;

    fused_gate_kernel<<<(B_ * C_) / ROWS_PER_BLK, 256>>>(x, W0, b0, W1, b1, out);
}